// round 9
// baseline (speedup 1.0000x reference)
#include <cuda_runtime.h>
#include <cuda_bf16.h>

#define NB 32
#define TC 256
#define NVOCAB 100
#define ND 384
#define DCH 128          // dims per main-kernel block (3-way D split)
#define NWARPS 16
#define NTILES 3
#define MAXT 2048
#define FB 4             // frames per group
#define MAXG (MAXT / FB) // 512 groups max
#define RWIN 32          // |t-center|>RWIN => z>=8 => rel contribution < 1e-13
#define WMAX 68          // max chars in a group window ((FB-1)+2*RWIN+1)
#define WWARPS 8         // warps per weight-kernel block

__device__ float g_center[NB][TC];
__device__ float g_invsig[NB][TC];
__device__ float g_wfac[NB][TC];
__device__ int   g_row[NB][TC];
__device__ int   g_totdur[NB];
__device__ int   g_fidx[NB][MAXT];

// Shared compact weight lists (written once, read by all 3 D-slabs)
__device__ int    g_nact[NB][MAXG];
__device__ float4 g_w4[NB][MAXG][WMAX];   // pre-normalized weights (4 frames)
__device__ int    g_off[NB][MAXG][WMAX];  // row * DCH

// ---------------- Phase 1: scan + per-char params ----------------
__global__ void ge_prep_kernel(const int* __restrict__ text,
                               const int* __restrict__ durs) {
    __shared__ int s[TC];
    int b = blockIdx.x, c = threadIdx.x;
    int d = durs[b * TC + c];
    s[c] = d;
    __syncthreads();
    #pragma unroll
    for (int off = 1; off < TC; off <<= 1) {
        int v = (c >= off) ? s[c - off] : 0;
        __syncthreads();
        s[c] += v;
        __syncthreads();
    }
    int incl = s[c];
    int start = incl - d;
    float df = (float)d;
    float sig = df * 0.5f + 1e-6f;
    float is = 1.0f / sig;
    g_center[b][c] = (float)start + df * 0.5f;
    g_invsig[b][c] = is;
    g_wfac[b][c]   = 0.3989422804014327f * is;
    g_row[b][c]    = text[b * TC + c];
    for (int f = start; f < incl; f++) g_fidx[b][f] = c;
    if (c == TC - 1) g_totdur[b] = incl;
}

// ---------------- Phase 2: per-group weights (one warp per group) ----------------
__global__ __launch_bounds__(WWARPS * 32)
void ge_weight_kernel(int Tt) {
    int b = blockIdx.y;
    int wid = threadIdx.x >> 5, lane = threadIdx.x & 31;
    int grp = blockIdx.x * WWARPS + wid;
    int t0 = grp * FB;
    if (t0 >= Tt) return;
    int totdur = g_totdur[b];
    if (t0 >= totdur) {                     // whole group time-pad
        if (lane == 0) g_nact[b][grp] = 0;
        return;
    }
    int nvalid = totdur - t0;
    if (nvalid > FB) nvalid = FB;

    int lo = g_fidx[b][max(t0 - RWIN, 0)];
    int hi = g_fidx[b][min(t0 + FB - 1 + RWIN, totdur - 1)] + 1;
    int win = hi - lo;

    float tt = (float)t0 + 0.5f;
    float4 W[3];
    float l0 = 0.f, l1 = 0.f, l2 = 0.f, l3 = 0.f;
    #pragma unroll
    for (int q = 0; q < 3; q++) {
        int j = q * 32 + lane;
        float4 w = make_float4(0.f, 0.f, 0.f, 0.f);
        if (j < win) {
            int c = lo + j;
            float is = g_invsig[b][c];
            float z0 = (tt - g_center[b][c]) * is;
            float z1 = z0 + is, z2 = z1 + is, z3 = z2 + is;
            float wf = g_wfac[b][c];
            w.x = __expf(-0.5f * z0 * z0) * wf;
            w.y = (1 < nvalid) ? __expf(-0.5f * z1 * z1) * wf : 0.f;
            w.z = (2 < nvalid) ? __expf(-0.5f * z2 * z2) * wf : 0.f;
            w.w = (3 < nvalid) ? __expf(-0.5f * z3 * z3) * wf : 0.f;
        }
        W[q] = w;
        l0 += w.x; l1 += w.y; l2 += w.z; l3 += w.w;
    }
    #pragma unroll
    for (int off = 16; off; off >>= 1) {
        l0 += __shfl_xor_sync(0xffffffffu, l0, off);
        l1 += __shfl_xor_sync(0xffffffffu, l1, off);
        l2 += __shfl_xor_sync(0xffffffffu, l2, off);
        l3 += __shfl_xor_sync(0xffffffffu, l3, off);
    }
    float i0 = 1.0f / (l0 + 1e-6f), i1 = 1.0f / (l1 + 1e-6f);
    float i2 = 1.0f / (l2 + 1e-6f), i3 = 1.0f / (l3 + 1e-6f);

    int nact = 0;
    #pragma unroll
    for (int q = 0; q < 3; q++) {
        int j = q * 32 + lane;
        float4 w = W[q];
        w.x *= i0; w.y *= i1; w.z *= i2; w.w *= i3;
        bool act = (j < win) &&
                   ((w.x > 1e-8f) | (w.y > 1e-8f) | (w.z > 1e-8f) | (w.w > 1e-8f));
        unsigned mask = __ballot_sync(0xffffffffu, act);
        if (act) {
            int pos = nact + __popc(mask & ((1u << lane) - 1u));
            g_w4[b][grp][pos]  = w;
            g_off[b][grp][pos] = g_row[b][lo + j] * DCH;
        }
        nact += __popc(mask);
    }
    if (lane == 0) g_nact[b][grp] = nact;
}

__device__ __forceinline__ void fma2(unsigned long long& acc,
                                     unsigned long long a,
                                     unsigned long long b) {
    asm("fma.rn.f32x2 %0, %1, %2, %0;" : "+l"(acc) : "l"(a), "l"(b));
}
__device__ __forceinline__ unsigned long long dup2(float x) {
    unsigned long long r;
    asm("mov.b64 %0, {%1, %1};" : "=l"(r) : "f"(x));
    return r;
}

// ---------------- Phase 3: gather + accumulate (3-way D split) ----------------
__global__ __launch_bounds__(NWARPS * 32, 2)
void ge_main_kernel(const float* __restrict__ embed,
                    float* __restrict__ out, int Tt) {
    extern __shared__ float smem[];
    float* semb  = smem;                          // NVOCAB*DCH floats (51.2 KB)
    float* s_wbuf = semb + NVOCAB * DCH;          // NWARPS*WMAX*4 floats
    int*   s_cbuf = (int*)(s_wbuf + NWARPS * WMAX * 4); // NWARPS*WMAX

    int tid = threadIdx.x;
    int b = blockIdx.y;
    int h = blockIdx.z;
    int totdur = g_totdur[b];
    int ngroups = (Tt + FB - 1) / FB;

    // Stage the 128-dim slab: row v -> semb[v*DCH ...]
    for (int i = tid; i < NVOCAB * 32; i += NWARPS * 32) {
        int v = i >> 5, c = i & 31;
        ((float4*)(semb + v * DCH))[c] =
            *((const float4*)(embed + v * ND + h * DCH) + c);
    }
    __syncthreads();

    int wid = tid >> 5, lane = tid & 31;
    float* wrow4 = s_wbuf + wid * (WMAX * 4);
    int*   coffw = s_cbuf + wid * WMAX;

    for (int grp = blockIdx.x * NWARPS + wid; grp < ngroups;
         grp += NTILES * NWARPS) {
        int t0 = grp * FB;
        int nvalid = totdur - t0;
        if (nvalid > FB) nvalid = FB;

        if (nvalid <= 0) {                        // whole group time-pad -> embed[0]
            float4 e0 = ((const float4*)semb)[lane];
            #pragma unroll
            for (int f = 0; f < FB; f++) {
                int t = t0 + f;
                if (t >= Tt) break;
                ((float4*)(out + ((size_t)b * Tt + t) * ND + h * DCH))[lane] = e0;
            }
            continue;
        }

        int nact = g_nact[b][grp];                // uniform LDG

        // stage compact list into shared (coalesced LDG.128)
        for (int j = lane; j < nact; j += 32) {
            *(float4*)&wrow4[j * 4] = g_w4[b][grp][j];
            coffw[j] = g_off[b][grp][j];
        }
        __syncwarp();

        // branch-free FMA pass: one LDS.128 slab per char, 4 frames served
        unsigned long long A[FB][2];
        #pragma unroll
        for (int f = 0; f < FB; f++) { A[f][0] = 0ULL; A[f][1] = 0ULL; }

        for (int k = 0; k < nact; k++) {
            float4 wv = *(float4*)&wrow4[k * 4];  // LDS.128 broadcast
            int off = coffw[k];                    // LDS broadcast
            ulonglong2 p = ((const ulonglong2*)(semb + off))[lane];
            unsigned long long W0 = dup2(wv.x), W1 = dup2(wv.y);
            unsigned long long W2 = dup2(wv.z), W3 = dup2(wv.w);
            fma2(A[0][0], W0, p.x); fma2(A[0][1], W0, p.y);
            fma2(A[1][0], W1, p.x); fma2(A[1][1], W1, p.y);
            fma2(A[2][0], W2, p.x); fma2(A[2][1], W2, p.y);
            fma2(A[3][0], W3, p.x); fma2(A[3][1], W3, p.y);
        }
        __syncwarp();   // wrow4/coffw reused next group

        // write (weights pre-normalized; coalesced 512B)
        #pragma unroll
        for (int f = 0; f < FB; f++) {
            int t = t0 + f;
            if (t >= Tt) break;
            float4* o = (float4*)(out + ((size_t)b * Tt + t) * ND + h * DCH);
            if (f < nvalid) {
                union { unsigned long long u[2]; float4 v; } cv;
                cv.u[0] = A[f][0];
                cv.u[1] = A[f][1];
                o[lane] = cv.v;
            } else {      // time-pad frame -> embed[0]
                o[lane] = ((const float4*)semb)[lane];
            }
        }
    }
}

extern "C" void kernel_launch(void* const* d_in, const int* in_sizes, int n_in,
                              void* d_out, int out_size) {
    const int*   text  = (const int*)d_in[0];
    const int*   durs  = (const int*)d_in[1];
    const float* embed = (const float*)d_in[2];
    float* out = (float*)d_out;

    int Tt = out_size / (NB * ND);
    int ngroups = (Tt + FB - 1) / FB;
    int gx = (ngroups + WWARPS - 1) / WWARPS;

    size_t smem_bytes = (size_t)(NVOCAB * DCH) * sizeof(float)
                        + (size_t)(NWARPS * WMAX * 4) * sizeof(float)
                        + (size_t)(NWARPS * WMAX) * sizeof(int);
    cudaFuncSetAttribute(ge_main_kernel,
                         cudaFuncAttributeMaxDynamicSharedMemorySize,
                         (int)smem_bytes);

    ge_prep_kernel<<<NB, TC>>>(text, durs);
    ge_weight_kernel<<<dim3(gx, NB), WWARPS * 32>>>(Tt);
    ge_main_kernel<<<dim3(NTILES, NB, 3), NWARPS * 32, smem_bytes>>>(embed, out, Tt);
}